// round 13
// baseline (speedup 1.0000x reference)
#include <cuda_runtime.h>
#include <stdint.h>

#define GRID_N   8
#define L_SITES  64
#define S_SIZE   9
#define N_PLAQ   64
#define LOCAL_D  2
#define M_DIM    128
#define BATCH    2048
#define NBLK     128         // (p, s8-half); <=148 SMs -> all resident, spin safe
#define NTHR     512
#define BPB      16          // batches packed per block
#define ROW_STR  132         // padded row stride (floats)
#define SP_STR   260         // padded sPart stride (256+4)
#define EPS_SLICE (LOCAL_D * M_DIM * S_SIZE)   // 2304 floats per plaquette

// Cross-block state (zero-initialized at load; self-reset every launch)
__device__ uint2    g_masks[BATCH];   // occupancy bitmasks, 16 KB
__device__ unsigned g_done;           // blocks that published masks+zeros
__device__ unsigned g_done2;          // blocks past the spin (for safe reset)

__global__ __launch_bounds__(NTHR, 1)
void fused_kernel(const int* __restrict__ inputs,
                  const float* __restrict__ eps,
                  float* __restrict__ out)
{
    const int tid  = threadIdx.x;
    const int blk  = blockIdx.x;
    const int p    = blk >> 1;        // plaquette
    const int half = blk & 1;         // s8 occupancy bit handled by this block

    __shared__ __align__(16) float sEps[EPS_SLICE];    // staged eps slice 9.2KB
    __shared__ __align__(16) float sSA[16 * ROW_STR];  // [s4..s7][m], s8 folded
    __shared__ __align__(16) float sSB[16 * ROW_STR];  // [s0..s3][m]
    __shared__ float sPart[8 * SP_STR];                // k-chunk partials
    __shared__ float sTab[256];                        // slice table

    // ---- A. Publish own 16 batch masks + zero own outputs (FIRST, fast) ---
    {
        const int lane = tid & 31;
        const int warp = tid >> 5;
        const int b    = blk * BPB + warp;
        const int* row = inputs + (size_t)b * L_SITES;
        const unsigned mlo = __ballot_sync(0xFFFFFFFFu, row[lane]      & 1);
        const unsigned mhi = __ballot_sync(0xFFFFFFFFu, row[lane + 32] & 1);
        if (lane == 0) {
            g_masks[b] = make_uint2(mlo, mhi);
            out[b] = 0.0f;
        }
    }
    __syncthreads();
    if (tid == 0) {
        __threadfence();              // release masks+zeros gpu-wide
        atomicAdd(&g_done, 1u);
    }

    // ---- B. Stage eps slice for this plaquette (coalesced) ----------------
    {
        const float* src = eps + (size_t)p * M_DIM * S_SIZE;   // o=0 chunk
        #pragma unroll
        for (int i = tid; i < EPS_SLICE / 2; i += NTHR)
            sEps[i] = __ldg(src + i);
        src = eps + (size_t)N_PLAQ * M_DIM * S_SIZE + (size_t)p * M_DIM * S_SIZE;
        #pragma unroll
        for (int i = tid; i < EPS_SLICE / 2; i += NTHR)
            sEps[EPS_SLICE / 2 + i] = __ldg(src + i);
    }
    __syncthreads();

    // ---- C. Phase 1: partial subset-products (reads from shared) ----------
    {
        const int m    = tid & 127;
        const int part = tid >> 7;    // 0,1: SB (8 rows each); 2,3: SA (8 rows)
        const float* e0p = sEps + m * S_SIZE;
        const float* e1p = sEps + EPS_SLICE / 2 + m * S_SIZE;
        float a0[S_SIZE], a1[S_SIZE];
        #pragma unroll
        for (int s = 0; s < S_SIZE; s++) { a0[s] = e0p[s]; a1[s] = e1p[s]; }

        if (part < 2) {
            const int base = part * 8;
            #pragma unroll
            for (int k = 0; k < 8; k++) {
                const int lo = base + k;
                float v = ((lo & 1) ? a1[0] : a0[0]);
                v *= ((lo & 2) ? a1[1] : a0[1]);
                v *= ((lo & 4) ? a1[2] : a0[2]);
                v *= ((lo & 8) ? a1[3] : a0[3]);
                sSB[lo * ROW_STR + m] = v;
            }
        } else {
            const int base = (part - 2) * 8;
            const float t8 = half ? a1[8] : a0[8];   // fold s8 factor
            #pragma unroll
            for (int k = 0; k < 8; k++) {
                const int h4 = base + k;             // bits s4..s7
                float v = ((h4 & 1) ? a1[4] : a0[4]);
                v *= ((h4 & 2) ? a1[5] : a0[5]);
                v *= ((h4 & 4) ? a1[6] : a0[6]);
                v *= ((h4 & 8) ? a1[7] : a0[7]);
                sSA[h4 * ROW_STR + m] = v * t8;
            }
        }
    }
    __syncthreads();

    // ---- D. Phase 2: 256 patterns, 2x2 register blocking, 8-way k-split ---
    {
        const int quad = tid >> 3;            // 0..63
        const int kc   = tid & 7;             // 16-float chunk of m
        const int hi0  = (quad >> 3) * 2;
        const int lo0  = (quad & 7) * 2;
        const float4* A0 = reinterpret_cast<const float4*>(sSA + hi0 * ROW_STR + kc * 16);
        const float4* A1 = reinterpret_cast<const float4*>(sSA + (hi0 + 1) * ROW_STR + kc * 16);
        const float4* B0 = reinterpret_cast<const float4*>(sSB + lo0 * ROW_STR + kc * 16);
        const float4* B1 = reinterpret_cast<const float4*>(sSB + (lo0 + 1) * ROW_STR + kc * 16);

        float a00 = 0.f, a01 = 0.f, a10 = 0.f, a11 = 0.f;
        #pragma unroll
        for (int i = 0; i < 4; i++) {
            const float4 x0 = A0[i], x1 = A1[i];
            const float4 y0 = B0[i], y1 = B1[i];
            a00 += x0.x*y0.x + x0.y*y0.y + x0.z*y0.z + x0.w*y0.w;
            a01 += x0.x*y1.x + x0.y*y1.y + x0.z*y1.z + x0.w*y1.w;
            a10 += x1.x*y0.x + x1.y*y0.y + x1.z*y0.z + x1.w*y0.w;
            a11 += x1.x*y1.x + x1.y*y1.y + x1.z*y1.z + x1.w*y1.w;
        }
        float* dst = sPart + kc * SP_STR;
        dst[(hi0    ) * 16 + lo0    ] = a00;
        dst[(hi0    ) * 16 + lo0 + 1] = a01;
        dst[(hi0 + 1) * 16 + lo0    ] = a10;
        dst[(hi0 + 1) * 16 + lo0 + 1] = a11;
    }
    __syncthreads();

    if (tid < 256) {
        float v = 0.0f;
        #pragma unroll
        for (int kc = 0; kc < 8; kc++) v += sPart[kc * SP_STR + tid];
        sTab[tid] = v;
    }

    // ---- E. Fast-path wait: all masks were published ~2K cycles ago -------
    if (tid == 0) {
        while (atomicAdd(&g_done, 0u) < NBLK) __nanosleep(32);
    }
    __syncthreads();       // also covers sTab writes
    __threadfence();       // acquire: see peer masks

    // ---- Self-reset counters for next launch ------------------------------
    if (tid == 0) {
        if (atomicAdd(&g_done2, 1u) == NBLK - 1u) {
            *(volatile unsigned*)&g_done  = 0u;
            *(volatile unsigned*)&g_done2 = 0u;
        }
    }

    // ---- F. Batch tail: predicate on s8 bit, scatter via red.add ----------
    const int pi = p >> 3;
    const int pj = p & 7;
    #pragma unroll
    for (int bb = 0; bb < 4; bb++) {
        const int b = bb * 512 + tid;
        const uint2 mk = g_masks[b];
        int trio[3];
        #pragma unroll
        for (int di = 0; di < 3; di++) {
            const int r = (pi + di) & 7;
            unsigned rb = (((r < 4) ? mk.x : mk.y) >> ((r & 3) * 8)) & 0xFFu;
            const unsigned dup = rb | (rb << 8);     // torus wraparound
            trio[di] = (int)((dup >> pj) & 7u);
        }
        const int s8bit = (trio[2] >> 2) & 1;        // site (pi+2, pj+2)
        if (s8bit == half) {
            const int pat8 = trio[0] | (trio[1] << 3) | ((trio[2] & 3) << 6);
            atomicAdd(&out[b], sTab[pat8]);          // no return use -> REDG
        }
    }
}

// ---------------------------------------------------------------------------
extern "C" void kernel_launch(void* const* d_in, const int* in_sizes, int n_in,
                              void* d_out, int out_size)
{
    // Identify inputs by element count (all distinct):
    //   inputs: 2048*64 = 131072 (int32), plaquettes: 576 (int32, unused —
    //   window indices are arithmetically fixed), epsilon: 147456 (float32)
    const int*   inputs = nullptr;
    const float* eps    = nullptr;
    for (int i = 0; i < n_in; i++) {
        if      (in_sizes[i] == BATCH * L_SITES) inputs = (const int*)d_in[i];
        else if (in_sizes[i] == LOCAL_D * N_PLAQ * M_DIM * S_SIZE)
                                                 eps    = (const float*)d_in[i];
    }
    float* out = (float*)d_out;

    fused_kernel<<<NBLK, NTHR>>>(inputs, eps, out);
}

// round 14
// speedup vs baseline: 1.2492x; 1.2492x over previous
#include <cuda_runtime.h>
#include <stdint.h>

#define GRID_N   8
#define L_SITES  64
#define S_SIZE   9
#define N_PLAQ   64
#define LOCAL_D  2
#define M_DIM    128
#define BATCH    2048
#define N_PAT    512
#define ROW_STR  132        // padded row stride (floats)
#define SP_STR   132        // padded sPart stride (128 pats + 4)

// T[p][pat], pat bit s = occupancy of window site s. 128 KB, L2-resident.
__device__ float g_table[N_PLAQ * N_PAT];

// ---------------------------------------------------------------------------
// Kernel 1: build table. Block = (plaquette, s7s8-quarter): 256 blocks.
// Each block builds 128 patterns (s0..s6 free, s7/s8 factors folded into SA).
// Phase-2 smem traffic per block ~80 KB (4x less than the 64-block version).
// ---------------------------------------------------------------------------
__global__ __launch_bounds__(512, 2)
void build_kernel(const float* __restrict__ eps)
{
    const int tid = threadIdx.x;
    const int p   = blockIdx.x >> 2;      // plaquette
    const int q   = blockIdx.x & 3;       // (s8<<1)|s7 occupancy bits

    __shared__ __align__(16) float sSA[8 * ROW_STR];   // [s4..s6][m], s7,s8 folded
    __shared__ __align__(16) float sSB[16 * ROW_STR];  // [s0..s3][m]
    __shared__ float sPart[16 * SP_STR];               // k-chunk partials

    // ---- Phase 1: partial subset-products into shared ---------------------
    {
        const int m    = tid & 127;
        const int part = tid >> 7;        // 0,1: SB 8 rows each; 2,3: SA 4 rows
        const float* e0p = eps + ((size_t)(0 * N_PLAQ + p) * M_DIM + m) * S_SIZE;
        const float* e1p = eps + ((size_t)(1 * N_PLAQ + p) * M_DIM + m) * S_SIZE;
        float a0[S_SIZE], a1[S_SIZE];
        #pragma unroll
        for (int s = 0; s < S_SIZE; s++) { a0[s] = __ldg(e0p + s); a1[s] = __ldg(e1p + s); }

        if (part < 2) {
            const int base = part * 8;
            #pragma unroll
            for (int k = 0; k < 8; k++) {
                const int lo = base + k;
                float v = ((lo & 1) ? a1[0] : a0[0]);
                v *= ((lo & 2) ? a1[1] : a0[1]);
                v *= ((lo & 4) ? a1[2] : a0[2]);
                v *= ((lo & 8) ? a1[3] : a0[3]);
                sSB[lo * ROW_STR + m] = v;
            }
        } else {
            const int base = (part - 2) * 4;
            const float f78 = ((q & 1) ? a1[7] : a0[7]) * ((q & 2) ? a1[8] : a0[8]);
            #pragma unroll
            for (int k = 0; k < 4; k++) {
                const int h3 = base + k;              // bits s4..s6
                float v = ((h3 & 1) ? a1[4] : a0[4]);
                v *= ((h3 & 2) ? a1[5] : a0[5]);
                v *= ((h3 & 4) ? a1[6] : a0[6]);
                sSA[h3 * ROW_STR + m] = v * f78;
            }
        }
    }
    __syncthreads();

    // ---- Phase 2: 128 patterns, 2x2 register blocking, 16-way k-split -----
    {
        const int quad = tid >> 4;            // 0..31 -> (hi pair, lo pair)
        const int kc   = tid & 15;            // 8-float chunk of m
        const int hi0  = (quad >> 3) * 2;     // 0,2,4,6   (s4..s6 pair)
        const int lo0  = (quad & 7) * 2;      // 0,2,..,14 (s0..s3 pair)
        const float4* A0 = reinterpret_cast<const float4*>(sSA + hi0 * ROW_STR + kc * 8);
        const float4* A1 = reinterpret_cast<const float4*>(sSA + (hi0 + 1) * ROW_STR + kc * 8);
        const float4* B0 = reinterpret_cast<const float4*>(sSB + lo0 * ROW_STR + kc * 8);
        const float4* B1 = reinterpret_cast<const float4*>(sSB + (lo0 + 1) * ROW_STR + kc * 8);

        float a00 = 0.f, a01 = 0.f, a10 = 0.f, a11 = 0.f;
        #pragma unroll
        for (int i = 0; i < 2; i++) {
            const float4 x0 = A0[i], x1 = A1[i];
            const float4 y0 = B0[i], y1 = B1[i];
            a00 += x0.x*y0.x + x0.y*y0.y + x0.z*y0.z + x0.w*y0.w;
            a01 += x0.x*y1.x + x0.y*y1.y + x0.z*y1.z + x0.w*y1.w;
            a10 += x1.x*y0.x + x1.y*y0.y + x1.z*y0.z + x1.w*y0.w;
            a11 += x1.x*y1.x + x1.y*y1.y + x1.z*y1.z + x1.w*y1.w;
        }
        float* dst = sPart + kc * SP_STR;
        dst[(hi0    ) * 16 + lo0    ] = a00;
        dst[(hi0    ) * 16 + lo0 + 1] = a01;
        dst[(hi0 + 1) * 16 + lo0    ] = a10;
        dst[(hi0 + 1) * 16 + lo0 + 1] = a11;
    }
    __syncthreads();

    // ---- Combine k-chunks, write 128-entry contiguous table slice ---------
    if (tid < 128) {
        float v = 0.0f;
        #pragma unroll
        for (int kc = 0; kc < 16; kc++) v += sPart[kc * SP_STR + tid];
        // pattern = tid(bits s0..s6) | s7<<7 | s8<<8  -> slice offset q*128
        g_table[p * N_PAT + q * 128 + tid] = v;
    }
}

// ---------------------------------------------------------------------------
// Kernel 2: one WARP per batch (unchanged from the best-measured R4 version).
// ---------------------------------------------------------------------------
#define WPB 16

__global__ __launch_bounds__(32 * WPB, 2)
void lookup_kernel(const int* __restrict__ inputs, float* __restrict__ out)
{
    const int lane = threadIdx.x & 31;
    const int warp = threadIdx.x >> 5;
    const int b    = blockIdx.x * WPB + warp;

    const int* row = inputs + (size_t)b * L_SITES;
    const unsigned mlo = __ballot_sync(0xFFFFFFFFu, row[lane]      & 1);
    const unsigned mhi = __ballot_sync(0xFFFFFFFFu, row[lane + 32] & 1);

    float acc = 0.0f;
    #pragma unroll
    for (int pp = 0; pp < 2; pp++) {
        const int p = lane + 32 * pp;
        const int i = p >> 3;
        const int j = p & 7;
        int pat = 0;
        #pragma unroll
        for (int di = 0; di < 3; di++) {
            const int r = (i + di) & 7;
            unsigned rb = (((r < 4) ? mlo : mhi) >> ((r & 3) * 8)) & 0xFFu;
            const unsigned dup = rb | (rb << 8);      // torus wraparound
            pat |= (int)((dup >> j) & 7u) << (3 * di);
        }
        acc += __ldg(&g_table[p * N_PAT + pat]);
    }

    #pragma unroll
    for (int off = 16; off > 0; off >>= 1)
        acc += __shfl_xor_sync(0xFFFFFFFFu, acc, off);

    if (lane == 0) out[b] = acc;
}

// ---------------------------------------------------------------------------
extern "C" void kernel_launch(void* const* d_in, const int* in_sizes, int n_in,
                              void* d_out, int out_size)
{
    // Identify inputs by element count (all distinct):
    //   inputs: 2048*64 = 131072 (int32), plaquettes: 576 (int32, unused —
    //   window indices are arithmetically fixed), epsilon: 147456 (float32)
    const int*   inputs = nullptr;
    const float* eps    = nullptr;
    for (int i = 0; i < n_in; i++) {
        if      (in_sizes[i] == BATCH * L_SITES) inputs = (const int*)d_in[i];
        else if (in_sizes[i] == LOCAL_D * N_PLAQ * M_DIM * S_SIZE)
                                                 eps    = (const float*)d_in[i];
    }
    float* out = (float*)d_out;

    build_kernel<<<N_PLAQ * 4, 512>>>(eps);
    lookup_kernel<<<BATCH / WPB, 32 * WPB>>>(inputs, out);
}